// round 13
// baseline (speedup 1.0000x reference)
#include <cuda_runtime.h>
#include <cuda_bf16.h>

#define BATCH 32
#define NAG   6
#define KS    256
#define QS    256
#define CHW   (512*32*32)       /* 524288 floats per (b,n) slab */
#define V4PB  (CHW/4)           /* 131072 float4 per (b,n) slab */
#define CHUNKS 8                /* attn kk-chunks per batch (32 rows each) */
#define TILES 4096              /* wsum tiles: 1024 float4 each */
#define GRID  740               /* 148 SMs x 5 blocks @48 regs: one wave */
#define FSTR  32                /* flag padding: one per 128B line */

// Scratch (allocation-free rule: __device__ globals). Zero-initialized at
// module load; all state is reset in-kernel so graph replays are identical.
__device__ float                 g_attn[BATCH * NAG];
__device__ float                 g_score[BATCH * NAG];
__device__ unsigned int          g_cnt[BATCH];
__device__ unsigned int          g_fin;
__device__ volatile unsigned int g_flag[BATCH * FSTR];

// ---------------------------------------------------------------------------
// Persistent fused kernel, grid = 740 x 256 (single wave -> no deadlock).
//  * blocks 0..255 first run one attn chunk (batch bid>>3):
//      k row prefetched at entry; query rows via warp dots; partial agent
//      scores atomicAdd'ed; ticketed finalizer: sparsemax -> g_attn ->
//      per-batch flag release.
//  * all blocks grid-stride over 4096 tiles; before each tile, thread 0
//      spins on that tile's batch flag (+syncthreads), then all threads read
//      the 6 weights via __ldcg (L2 — g_attn is produced on another SM, a
//      plain load could hit a stale L1 line cached by an earlier tile!),
//      and run the 4x float4 weighted sum, skipping zero-weight agents.
//  * last finishing block resets flags/g_fin for the next graph replay.
// ---------------------------------------------------------------------------
__global__ void __launch_bounds__(256)
fused_kernel(const float* __restrict__ q,
             const float* __restrict__ k,
             const float* __restrict__ v,
             const float* __restrict__ W,
             const float* __restrict__ bias,
             float* __restrict__ out,
             float* __restrict__ out_attn,
             int write_attn) {
    const int bid  = blockIdx.x;
    const int t    = threadIdx.x;
    const int wid  = t >> 5, lane = t & 31;

    __shared__ float4 sq4[QS / 4];
    __shared__ float  squery[32];

    // ================= attn phase (blocks 0..255 only) ====================
    if (bid < BATCH * CHUNKS) {
        const int ab     = bid >> 3;
        const int kkbase = (bid & 7) << 5;

        // prefetch this warp's k element (overlaps the q/W loads below)
        float kval = 0.0f;
        if (wid < NAG)
            kval = k[(ab * NAG + wid) * KS + kkbase + lane];

        if (t < QS / 4) sq4[t] = ((const float4*)(q + ab * QS))[t];
        __syncthreads();

        // warp `wid` computes 4 query rows, 2 at a time
        {
            const int r0 = kkbase + (wid << 2);
            const float4 q0 = sq4[lane], q1 = sq4[lane + 32];
            #pragma unroll
            for (int h = 0; h < 2; h++) {
                const int ra = r0 + 2 * h;
                const float4* wa = (const float4*)(W + ra * QS);
                const float4* wb = (const float4*)(W + (ra + 1) * QS);
                float4 a0 = wa[lane], a1 = wa[lane + 32];
                float4 b0 = wb[lane], b1 = wb[lane + 32];
                float sa = a0.x * q0.x + a0.y * q0.y + a0.z * q0.z + a0.w * q0.w
                         + a1.x * q1.x + a1.y * q1.y + a1.z * q1.z + a1.w * q1.w;
                float sb = b0.x * q0.x + b0.y * q0.y + b0.z * q0.z + b0.w * q0.w
                         + b1.x * q1.x + b1.y * q1.y + b1.z * q1.z + b1.w * q1.w;
                #pragma unroll
                for (int o = 16; o; o >>= 1) {
                    sa += __shfl_xor_sync(0xffffffffu, sa, o);
                    sb += __shfl_xor_sync(0xffffffffu, sb, o);
                }
                if (lane == 0) {
                    squery[(wid << 2) + 2 * h]     = sa + bias[ra];
                    squery[(wid << 2) + 2 * h + 1] = sb + bias[ra + 1];
                }
            }
        }
        __syncthreads();

        // 6 warps -> partial agent scores (k already in registers)
        if (wid < NAG) {
            float p = kval * squery[lane];
            #pragma unroll
            for (int o = 16; o; o >>= 1) p += __shfl_xor_sync(0xffffffffu, p, o);
            if (lane == 0) atomicAdd(&g_score[ab * NAG + wid], p);
        }

        __threadfence();
        if (t == 0 && atomicAdd(&g_cnt[ab], 1u) == CHUNKS - 1) {
            __threadfence();                      // acquire all partials
            float z[NAG], zs[NAG];
            #pragma unroll
            for (int n = 0; n < NAG; n++) {
                z[n] = g_score[ab * NAG + n];
                zs[n] = z[n];
                g_score[ab * NAG + n] = 0.0f;     // reset for next replay
            }
            g_cnt[ab] = 0u;
            #pragma unroll
            for (int i = 1; i < NAG; i++) {       // insertion sort, descending
                float key = zs[i]; int j = i - 1;
                while (j >= 0 && zs[j] < key) { zs[j + 1] = zs[j]; j--; }
                zs[j + 1] = key;
            }
            float cs[NAG], run = 0.f;
            #pragma unroll
            for (int r = 0; r < NAG; r++) { run += zs[r]; cs[r] = run; }
            int kk = 0;
            #pragma unroll
            for (int r = 1; r <= NAG; r++)
                if (1.0f + (float)r * zs[r - 1] > cs[r - 1]) kk++;
            const float tau = (cs[kk - 1] - 1.0f) / (float)kk;
            #pragma unroll
            for (int n = 0; n < NAG; n++) {
                float p = fmaxf(z[n] - tau, 0.0f);
                g_attn[ab * NAG + n] = p;
                if (write_attn) out_attn[ab * NAG + n] = p;
            }
            __threadfence();                      // publish before release
            g_flag[ab * FSTR] = 1u;
        }
        __syncthreads();
    }

    // ================= persistent wsum loop ===============================
    for (int tau = bid; tau < TILES; tau += GRID) {
        const int b    = tau >> 7;                       // 128 tiles/batch
        const int base = ((tau & 127) << 10) + t;        // float4 idx in slab

        // wait for this tile's batch (thread-0 spin, proven-safe pattern)
        if (t == 0) {
            while (g_flag[b * FSTR] == 0u) __nanosleep(64);
        }
        __syncthreads();

        // weights via __ldcg: L2-coherent (producer is on another SM; a plain
        // load could hit a stale L1 line cached by an earlier tile).
        float sw[NAG];
        #pragma unroll
        for (int n = 0; n < NAG; n++) sw[n] = __ldcg(&g_attn[b * NAG + n]);

        const float4* vb = (const float4*)v + (b * (NAG * V4PB) + base);

        float4 acc0 = make_float4(0.f, 0.f, 0.f, 0.f);
        float4 acc1 = acc0, acc2 = acc0, acc3 = acc0;

        #pragma unroll
        for (int n = 0; n < NAG; n++) {
            const float w = sw[n];
            if (w != 0.0f) {                  // block-uniform branch
                const float4* p = vb + n * V4PB;
                float4 x0 = __ldcs(p);
                float4 x1 = __ldcs(p + 256);
                float4 x2 = __ldcs(p + 512);
                float4 x3 = __ldcs(p + 768);
                acc0.x = fmaf(w, x0.x, acc0.x); acc0.y = fmaf(w, x0.y, acc0.y);
                acc0.z = fmaf(w, x0.z, acc0.z); acc0.w = fmaf(w, x0.w, acc0.w);
                acc1.x = fmaf(w, x1.x, acc1.x); acc1.y = fmaf(w, x1.y, acc1.y);
                acc1.z = fmaf(w, x1.z, acc1.z); acc1.w = fmaf(w, x1.w, acc1.w);
                acc2.x = fmaf(w, x2.x, acc2.x); acc2.y = fmaf(w, x2.y, acc2.y);
                acc2.z = fmaf(w, x2.z, acc2.z); acc2.w = fmaf(w, x2.w, acc2.w);
                acc3.x = fmaf(w, x3.x, acc3.x); acc3.y = fmaf(w, x3.y, acc3.y);
                acc3.z = fmaf(w, x3.z, acc3.z); acc3.w = fmaf(w, x3.w, acc3.w);
            }
        }

        float4* ob = (float4*)out + (b * V4PB + base);
        __stcs(ob,       acc0);
        __stcs(ob + 256, acc1);
        __stcs(ob + 512, acc2);
        __stcs(ob + 768, acc3);
    }

    // -------- reset flags/counter for the next graph replay ---------------
    __syncthreads();
    if (t == 0 && atomicAdd(&g_fin, 1u) == GRID - 1) {
        g_fin = 0u;
        #pragma unroll
        for (int b2 = 0; b2 < BATCH; b2++) g_flag[b2 * FSTR] = 0u;
    }
}

// ---------------------------------------------------------------------------
extern "C" void kernel_launch(void* const* d_in, const int* in_sizes, int n_in,
                              void* d_out, int out_size) {
    const float* q    = (const float*)d_in[0];
    const float* k    = (const float*)d_in[1];
    const float* v    = (const float*)d_in[2];
    const float* W    = (const float*)d_in[3];
    const float* bias = (const float*)d_in[4];

    float* out = (float*)d_out;
    const long long out_main = (long long)BATCH * CHW;        // 16777216
    const int write_attn = (out_size >= out_main + BATCH * NAG) ? 1 : 0;
    float* out_attn = out + out_main;

    fused_kernel<<<GRID, 256>>>(q, k, v, W, bias, out, out_attn, write_attn);
}

// round 14
// speedup vs baseline: 1.3043x; 1.3043x over previous
#include <cuda_runtime.h>
#include <cuda_bf16.h>

#define BATCH 32
#define NAG   6
#define KS    256
#define QS    256
#define CHW   (512*32*32)       /* 524288 floats per (b,n) slab */
#define V4PB  (CHW/4)           /* 131072 float4 per (b,n) slab */
#define CHUNKS 8                /* attn kk-chunks per batch (32 rows each) */
#define TPB   128               /* wsum tiles per batch (1024 float4 each) */
#define BPB   23                /* wsum blocks per batch */
#define GRID  (BATCH * BPB)     /* 736 <= 740 one-wave capacity */
#define FSTR  32                /* flag padding: one per 128B line */

// Scratch (allocation-free rule: __device__ globals). Zero-initialized at
// module load; all state is reset in-kernel so graph replays are identical.
__device__ float                 g_attn[BATCH * NAG];
__device__ float                 g_score[BATCH * NAG];
__device__ unsigned int          g_cnt[BATCH];
__device__ unsigned int          g_fin;
__device__ volatile unsigned int g_flag[BATCH * FSTR];

// ---------------------------------------------------------------------------
// Persistent fused kernel, grid = 736 x 256 (single wave).
//  * blocks 0..255 first run one attn chunk (batch bid>>3): k prefetched,
//      query rows via warp dots, partial scores atomicAdd'ed, ticketed
//      finalizer: sparsemax -> g_attn -> per-batch flag release.
//  * wsum: each block owns 5-6 tiles of ONE batch (b = bid/23). It waits
//      once on that batch's flag (thread-0 spin + one syncthreads), reads
//      the 6 weights once via __ldcg (L2-coherent; producer is on another
//      SM), resolves the single/multi-agent branch once, then loops over
//      its tiles with NO barriers (cross-tile load pipelining preserved).
//  * last finishing block resets flags/g_fin for the next graph replay.
// ---------------------------------------------------------------------------
__global__ void __launch_bounds__(256)
fused_kernel(const float* __restrict__ q,
             const float* __restrict__ k,
             const float* __restrict__ v,
             const float* __restrict__ W,
             const float* __restrict__ bias,
             float* __restrict__ out,
             float* __restrict__ out_attn,
             int write_attn) {
    const int bid  = blockIdx.x;
    const int t    = threadIdx.x;
    const int wid  = t >> 5, lane = t & 31;

    __shared__ float4 sq4[QS / 4];
    __shared__ float  squery[32];

    // ================= attn phase (blocks 0..255 only) ====================
    if (bid < BATCH * CHUNKS) {
        const int ab     = bid >> 3;
        const int kkbase = (bid & 7) << 5;

        // prefetch this warp's k element (overlaps the q/W loads below)
        float kval = 0.0f;
        if (wid < NAG)
            kval = k[(ab * NAG + wid) * KS + kkbase + lane];

        if (t < QS / 4) sq4[t] = ((const float4*)(q + ab * QS))[t];
        __syncthreads();

        // warp `wid` computes 4 query rows, 2 at a time
        {
            const int r0 = kkbase + (wid << 2);
            const float4 q0 = sq4[lane], q1 = sq4[lane + 32];
            #pragma unroll
            for (int h = 0; h < 2; h++) {
                const int ra = r0 + 2 * h;
                const float4* wa = (const float4*)(W + ra * QS);
                const float4* wb = (const float4*)(W + (ra + 1) * QS);
                float4 a0 = wa[lane], a1 = wa[lane + 32];
                float4 b0 = wb[lane], b1 = wb[lane + 32];
                float sa = a0.x * q0.x + a0.y * q0.y + a0.z * q0.z + a0.w * q0.w
                         + a1.x * q1.x + a1.y * q1.y + a1.z * q1.z + a1.w * q1.w;
                float sb = b0.x * q0.x + b0.y * q0.y + b0.z * q0.z + b0.w * q0.w
                         + b1.x * q1.x + b1.y * q1.y + b1.z * q1.z + b1.w * q1.w;
                #pragma unroll
                for (int o = 16; o; o >>= 1) {
                    sa += __shfl_xor_sync(0xffffffffu, sa, o);
                    sb += __shfl_xor_sync(0xffffffffu, sb, o);
                }
                if (lane == 0) {
                    squery[(wid << 2) + 2 * h]     = sa + bias[ra];
                    squery[(wid << 2) + 2 * h + 1] = sb + bias[ra + 1];
                }
            }
        }
        __syncthreads();

        // 6 warps -> partial agent scores (k already in registers)
        if (wid < NAG) {
            float p = kval * squery[lane];
            #pragma unroll
            for (int o = 16; o; o >>= 1) p += __shfl_xor_sync(0xffffffffu, p, o);
            if (lane == 0) atomicAdd(&g_score[ab * NAG + wid], p);
        }

        __threadfence();
        if (t == 0 && atomicAdd(&g_cnt[ab], 1u) == CHUNKS - 1) {
            __threadfence();                      // acquire all partials
            float z[NAG], zs[NAG];
            #pragma unroll
            for (int n = 0; n < NAG; n++) {
                z[n] = g_score[ab * NAG + n];
                zs[n] = z[n];
                g_score[ab * NAG + n] = 0.0f;     // reset for next replay
            }
            g_cnt[ab] = 0u;
            #pragma unroll
            for (int i = 1; i < NAG; i++) {       // insertion sort, descending
                float key = zs[i]; int j = i - 1;
                while (j >= 0 && zs[j] < key) { zs[j + 1] = zs[j]; j--; }
                zs[j + 1] = key;
            }
            float cs[NAG], run = 0.f;
            #pragma unroll
            for (int r = 0; r < NAG; r++) { run += zs[r]; cs[r] = run; }
            int kk = 0;
            #pragma unroll
            for (int r = 1; r <= NAG; r++)
                if (1.0f + (float)r * zs[r - 1] > cs[r - 1]) kk++;
            const float tau = (cs[kk - 1] - 1.0f) / (float)kk;
            #pragma unroll
            for (int n = 0; n < NAG; n++) {
                float p = fmaxf(z[n] - tau, 0.0f);
                g_attn[ab * NAG + n] = p;
                if (write_attn) out_attn[ab * NAG + n] = p;
            }
            __threadfence();                      // publish before release
            g_flag[ab * FSTR] = 1u;
        }
        __syncthreads();
    }

    // ================= wsum phase: one batch per block ====================
    const int b    = bid / BPB;
    const int idx  = bid - b * BPB;
    const int tile0 = (idx * TPB) / BPB;            // 5 or 6 tiles
    const int tile1 = ((idx + 1) * TPB) / BPB;

    // wait ONCE for this block's batch (thread-0 spin + single barrier)
    if (t == 0) {
        while (g_flag[b * FSTR] == 0u) __nanosleep(64);
    }
    __syncthreads();

    // weights once, L2-coherent; resolve the agent pattern once
    float sw[NAG];
    #pragma unroll
    for (int n = 0; n < NAG; n++) sw[n] = __ldcg(&g_attn[b * NAG + n]);
    int nz = 0, n0 = 0;
    #pragma unroll
    for (int n = 0; n < NAG; n++)
        if (sw[n] != 0.0f) { if (nz == 0) n0 = n; nz++; }

    const float4* vslab = (const float4*)v + b * (NAG * V4PB);
    float4*       oslab = (float4*)out    + b * V4PB;

    if (nz == 1) {
        // ---- dominant path: scale-copy, branchless, software-pipelined ----
        const float w = sw[n0];
        const float4* p0 = vslab + n0 * V4PB;
        for (int tile = tile0; tile < tile1; tile++) {
            const int base = (tile << 10) + t;
            float4 x0 = __ldcs(p0 + base);
            float4 x1 = __ldcs(p0 + base + 256);
            float4 x2 = __ldcs(p0 + base + 512);
            float4 x3 = __ldcs(p0 + base + 768);
            float4 r0, r1, r2, r3;
            r0.x = w * x0.x; r0.y = w * x0.y; r0.z = w * x0.z; r0.w = w * x0.w;
            r1.x = w * x1.x; r1.y = w * x1.y; r1.z = w * x1.z; r1.w = w * x1.w;
            r2.x = w * x2.x; r2.y = w * x2.y; r2.z = w * x2.z; r2.w = w * x2.w;
            r3.x = w * x3.x; r3.y = w * x3.y; r3.z = w * x3.z; r3.w = w * x3.w;
            __stcs(oslab + base,       r0);
            __stcs(oslab + base + 256, r1);
            __stcs(oslab + base + 512, r2);
            __stcs(oslab + base + 768, r3);
        }
    } else {
        // ---- rare path: multi-agent accumulate ----------------------------
        for (int tile = tile0; tile < tile1; tile++) {
            const int base = (tile << 10) + t;
            float4 acc0 = make_float4(0.f, 0.f, 0.f, 0.f);
            float4 acc1 = acc0, acc2 = acc0, acc3 = acc0;
            #pragma unroll
            for (int n = 0; n < NAG; n++) {
                const float w = sw[n];
                if (w != 0.0f) {
                    const float4* p = vslab + (n * V4PB + base);
                    float4 x0 = __ldcs(p);
                    float4 x1 = __ldcs(p + 256);
                    float4 x2 = __ldcs(p + 512);
                    float4 x3 = __ldcs(p + 768);
                    acc0.x = fmaf(w, x0.x, acc0.x); acc0.y = fmaf(w, x0.y, acc0.y);
                    acc0.z = fmaf(w, x0.z, acc0.z); acc0.w = fmaf(w, x0.w, acc0.w);
                    acc1.x = fmaf(w, x1.x, acc1.x); acc1.y = fmaf(w, x1.y, acc1.y);
                    acc1.z = fmaf(w, x1.z, acc1.z); acc1.w = fmaf(w, x1.w, acc1.w);
                    acc2.x = fmaf(w, x2.x, acc2.x); acc2.y = fmaf(w, x2.y, acc2.y);
                    acc2.z = fmaf(w, x2.z, acc2.z); acc2.w = fmaf(w, x2.w, acc2.w);
                    acc3.x = fmaf(w, x3.x, acc3.x); acc3.y = fmaf(w, x3.y, acc3.y);
                    acc3.z = fmaf(w, x3.z, acc3.z); acc3.w = fmaf(w, x3.w, acc3.w);
                }
            }
            __stcs(oslab + base,       acc0);
            __stcs(oslab + base + 256, acc1);
            __stcs(oslab + base + 512, acc2);
            __stcs(oslab + base + 768, acc3);
        }
    }

    // -------- reset flags/counter for the next graph replay ---------------
    __syncthreads();
    if (t == 0 && atomicAdd(&g_fin, 1u) == GRID - 1) {
        g_fin = 0u;
        #pragma unroll
        for (int b2 = 0; b2 < BATCH; b2++) g_flag[b2 * FSTR] = 0u;
    }
}

// ---------------------------------------------------------------------------
extern "C" void kernel_launch(void* const* d_in, const int* in_sizes, int n_in,
                              void* d_out, int out_size) {
    const float* q    = (const float*)d_in[0];
    const float* k    = (const float*)d_in[1];
    const float* v    = (const float*)d_in[2];
    const float* W    = (const float*)d_in[3];
    const float* bias = (const float*)d_in[4];

    float* out = (float*)d_out;
    const long long out_main = (long long)BATCH * CHW;        // 16777216
    const int write_attn = (out_size >= out_main + BATCH * NAG) ? 1 : 0;
    float* out_attn = out + out_main;

    fused_kernel<<<GRID, 256>>>(q, k, v, W, bias, out, out_attn, write_attn);
}

// round 15
// speedup vs baseline: 1.7739x; 1.3600x over previous
#include <cuda_runtime.h>
#include <cuda_bf16.h>

#define BATCH 32
#define NAG   6
#define KS    256
#define QS    256
#define CHW   (512*32*32)       /* 524288 floats per (b,n) slab */
#define V4PB  (CHW/4)           /* 131072 float4 per (b,n) slab */
#define CHUNKS 8                /* attn kk-chunks per batch (32 rows each) */

typedef unsigned long long u64;

// Scratch (allocation-free rule: __device__ globals). Counters reset in the
// finalizer so every graph replay starts from identical state. The kernel
// boundary between attn and wsum flushes L1 and orders all writes, so wsum
// reads these with plain loads.
__device__ float        g_attn[BATCH * NAG];
__device__ u64          g_pack[BATCH];       // hi32: 1..6 = n0+1, 7 = multi
                                             // lo32: float bits of w[n0]
__device__ float        g_score[BATCH * NAG];
__device__ unsigned int g_cnt[BATCH];

// ---------------------------------------------------------------------------
// Kernel 1: attention. grid = 256 blocks (8 chunks per batch), 256 threads.
// Block (b,c): query rows kk in [32c,32c+32) via warp-per-row dots (W read is
// fully parallel across 256 blocks); partial agent scores atomicAdd'ed; the
// ticketed finalizer runs sparsemax, writes g_attn/g_pack/out_attn, and
// resets the counters for the next graph replay.
// ---------------------------------------------------------------------------
__global__ void __launch_bounds__(256)
attn_kernel(const float* __restrict__ q,
            const float* __restrict__ k,
            const float* __restrict__ W,
            const float* __restrict__ bias,
            float* __restrict__ out_attn,
            int write_attn) {
    const int bid    = blockIdx.x;
    const int ab     = bid >> 3;
    const int kkbase = (bid & 7) << 5;
    const int t      = threadIdx.x;
    const int wid    = t >> 5, lane = t & 31;

    __shared__ float4 sq4[QS / 4];
    __shared__ float  squery[32];

    // prefetch this warp's k element (overlaps the q/W loads below)
    float kval = 0.0f;
    if (wid < NAG)
        kval = k[(ab * NAG + wid) * KS + kkbase + lane];

    if (t < QS / 4) sq4[t] = ((const float4*)(q + ab * QS))[t];
    __syncthreads();

    // warp `wid` computes 4 query rows, 2 at a time
    {
        const int r0 = kkbase + (wid << 2);
        const float4 q0 = sq4[lane], q1 = sq4[lane + 32];
        #pragma unroll
        for (int h = 0; h < 2; h++) {
            const int ra = r0 + 2 * h;
            const float4* wa = (const float4*)(W + ra * QS);
            const float4* wb = (const float4*)(W + (ra + 1) * QS);
            float4 a0 = wa[lane], a1 = wa[lane + 32];
            float4 b0 = wb[lane], b1 = wb[lane + 32];
            float sa = a0.x * q0.x + a0.y * q0.y + a0.z * q0.z + a0.w * q0.w
                     + a1.x * q1.x + a1.y * q1.y + a1.z * q1.z + a1.w * q1.w;
            float sb = b0.x * q0.x + b0.y * q0.y + b0.z * q0.z + b0.w * q0.w
                     + b1.x * q1.x + b1.y * q1.y + b1.z * q1.z + b1.w * q1.w;
            #pragma unroll
            for (int o = 16; o; o >>= 1) {
                sa += __shfl_xor_sync(0xffffffffu, sa, o);
                sb += __shfl_xor_sync(0xffffffffu, sb, o);
            }
            if (lane == 0) {
                squery[(wid << 2) + 2 * h]     = sa + bias[ra];
                squery[(wid << 2) + 2 * h + 1] = sb + bias[ra + 1];
            }
        }
    }
    __syncthreads();

    // 6 warps -> partial agent scores (k already in registers)
    if (wid < NAG) {
        float p = kval * squery[lane];
        #pragma unroll
        for (int o = 16; o; o >>= 1) p += __shfl_xor_sync(0xffffffffu, p, o);
        if (lane == 0) atomicAdd(&g_score[ab * NAG + wid], p);
    }

    __threadfence();
    if (t == 0 && atomicAdd(&g_cnt[ab], 1u) == CHUNKS - 1) {
        __threadfence();                      // acquire all partials
        float z[NAG], zs[NAG];
        #pragma unroll
        for (int n = 0; n < NAG; n++) {
            z[n] = g_score[ab * NAG + n];
            zs[n] = z[n];
            g_score[ab * NAG + n] = 0.0f;     // reset for next replay
        }
        g_cnt[ab] = 0u;
        #pragma unroll
        for (int i = 1; i < NAG; i++) {       // insertion sort, descending
            float key = zs[i]; int j = i - 1;
            while (j >= 0 && zs[j] < key) { zs[j + 1] = zs[j]; j--; }
            zs[j + 1] = key;
        }
        float cs[NAG], run = 0.f;
        #pragma unroll
        for (int r = 0; r < NAG; r++) { run += zs[r]; cs[r] = run; }
        int kk = 0;
        #pragma unroll
        for (int r = 1; r <= NAG; r++)
            if (1.0f + (float)r * zs[r - 1] > cs[r - 1]) kk++;
        const float tau = (cs[kk - 1] - 1.0f) / (float)kk;

        int   nz = 0, n0 = 0;
        float w0 = 0.0f;
        #pragma unroll
        for (int n = 0; n < NAG; n++) {
            float p = fmaxf(z[n] - tau, 0.0f);
            g_attn[ab * NAG + n] = p;
            if (write_attn) out_attn[ab * NAG + n] = p;
            if (p != 0.0f) { if (nz == 0) { n0 = n; w0 = p; } nz++; }
        }
        const unsigned code = (nz == 1) ? (unsigned)(n0 + 1) : 7u;
        g_pack[ab] = ((u64)code << 32) | (u64)__float_as_uint(w0);
    }
}

// ---------------------------------------------------------------------------
// Kernel 2: weighted sum. grid = 2048 x 256, tile = 2048 float4 per block.
// Dominant path (sparsemax support k==1, the typical case): accumulator-free
// 8x float4 scale-copy -> 8 loads in flight per thread with no acc register
// bank (the R3 failure was 8 loads PLUS 8 acc float4s). ~41 KB in flight/SM
// at 5 blocks/SM covers the DRAM latency-bandwidth product.
// Rare path (k>=2): two 4-accumulator halves over the 6 agents.
// ---------------------------------------------------------------------------
__global__ void __launch_bounds__(256)
wsum_kernel(const float* __restrict__ v, float* __restrict__ out) {
    const int bid  = blockIdx.x;
    const int t    = threadIdx.x;
    const int b    = bid >> 6;                        // 64 blocks/batch
    const int base = ((bid & 63) << 11) + t;          // float4 idx in slab

    const u64 pk   = g_pack[b];                       // fresh L1 post-launch
    const int code = (int)(pk >> 32);

    const float4* vslab = (const float4*)v + b * (NAG * V4PB);
    float4*       ob    = (float4*)out    + (b * V4PB + base);

    if (code <= NAG) {
        // ---- dominant: single nonzero agent -> scale-copy, MLP=8 ---------
        const float w = __uint_as_float((unsigned)pk);
        const float4* p = vslab + ((code - 1) * V4PB + base);
        float4 x[8];
        #pragma unroll
        for (int i = 0; i < 8; i++) x[i] = __ldcs(p + (i << 8));
        #pragma unroll
        for (int i = 0; i < 8; i++) {
            float4 r;
            r.x = w * x[i].x; r.y = w * x[i].y;
            r.z = w * x[i].z; r.w = w * x[i].w;
            __stcs(ob + (i << 8), r);
        }
    } else {
        // ---- rare: multi-agent accumulate, two halves of 4 ----------------
        float sw[NAG];
        #pragma unroll
        for (int n = 0; n < NAG; n++) sw[n] = g_attn[b * NAG + n];
        #pragma unroll
        for (int h = 0; h < 2; h++) {
            const int off = h << 10;                  // 0 or 1024 float4
            float4 acc0 = make_float4(0.f, 0.f, 0.f, 0.f);
            float4 acc1 = acc0, acc2 = acc0, acc3 = acc0;
            #pragma unroll
            for (int n = 0; n < NAG; n++) {
                const float w = sw[n];
                if (w != 0.0f) {                      // block-uniform branch
                    const float4* p = vslab + (n * V4PB + base + off);
                    float4 x0 = __ldcs(p);
                    float4 x1 = __ldcs(p + 256);
                    float4 x2 = __ldcs(p + 512);
                    float4 x3 = __ldcs(p + 768);
                    acc0.x = fmaf(w, x0.x, acc0.x); acc0.y = fmaf(w, x0.y, acc0.y);
                    acc0.z = fmaf(w, x0.z, acc0.z); acc0.w = fmaf(w, x0.w, acc0.w);
                    acc1.x = fmaf(w, x1.x, acc1.x); acc1.y = fmaf(w, x1.y, acc1.y);
                    acc1.z = fmaf(w, x1.z, acc1.z); acc1.w = fmaf(w, x1.w, acc1.w);
                    acc2.x = fmaf(w, x2.x, acc2.x); acc2.y = fmaf(w, x2.y, acc2.y);
                    acc2.z = fmaf(w, x2.z, acc2.z); acc2.w = fmaf(w, x2.w, acc2.w);
                    acc3.x = fmaf(w, x3.x, acc3.x); acc3.y = fmaf(w, x3.y, acc3.y);
                    acc3.z = fmaf(w, x3.z, acc3.z); acc3.w = fmaf(w, x3.w, acc3.w);
                }
            }
            __stcs(ob + off,       acc0);
            __stcs(ob + off + 256, acc1);
            __stcs(ob + off + 512, acc2);
            __stcs(ob + off + 768, acc3);
        }
    }
}

// ---------------------------------------------------------------------------
extern "C" void kernel_launch(void* const* d_in, const int* in_sizes, int n_in,
                              void* d_out, int out_size) {
    const float* q    = (const float*)d_in[0];
    const float* k    = (const float*)d_in[1];
    const float* v    = (const float*)d_in[2];
    const float* W    = (const float*)d_in[3];
    const float* bias = (const float*)d_in[4];

    float* out = (float*)d_out;
    const long long out_main = (long long)BATCH * CHW;        // 16777216
    const int write_attn = (out_size >= out_main + BATCH * NAG) ? 1 : 0;
    float* out_attn = out + out_main;

    attn_kernel<<<BATCH * CHUNKS, 256>>>(q, k, W, bias, out_attn, write_attn);

    const int blocks = (BATCH * V4PB) / (256 * 8);            // 2048
    wsum_kernel<<<blocks, 256>>>(v, out);
}